// round 16
// baseline (speedup 1.0000x reference)
#include <cuda_runtime.h>
#include <cuda_fp16.h>
#include <cstdint>

#define N_TOTAL 100000
#define DIM     128
#define N_USER  50000
#define N_ENT   50000
#define E_MAX   1700000
#define RB      64                 // rows per block
#define BLOCKS_ENT 782             // ceil(50000/64)
#define AS_PITCH 132
#define SCAN_TILE 1024
#define NBLK 98                    // ceil(100000/1024)

// Scratch (device globals; zero-initialized at load).
// g_cnt re-zeroed by fused_kernel tail each call.
__device__ int      g_cnt[N_TOTAL];
__device__ int      g_off[N_TOTAL + 1];
__device__ int      g_cur[N_TOTAL];
__device__ int      g_bsum[NBLK];
__device__ int      g_bpre[NBLK];
__device__ int2     g_edge[E_MAX];               // {col | (r&7)<<17, val_bits}
__device__ unsigned g_wt[2][DIM * DIM];          // W tf32, permuted [k][lq*16+n]
__device__ __half   g_ebs_h[(size_t)N_TOTAL * DIM];  // fp16 embeddings (25.6MB)

__device__ __forceinline__ unsigned cvt_tf32(float f) {
    unsigned r;
    asm("cvt.rna.tf32.f32 %0, %1;" : "=r"(r) : "f"(f));
    return r;
}

// ---------------------------------------------------------------------------
// 1) prep: ebs fp32->fp16, W->tf32 permuted, row histogram  (one kernel)
// ---------------------------------------------------------------------------
__global__ void prep_kernel(const int* __restrict__ rows_u,
                            const int* __restrict__ rows_i,
                            const float* __restrict__ Wu,
                            const float* __restrict__ Wi,
                            const float* __restrict__ ebs,
                            int E_u, int E_i) {
    int e = blockIdx.x * blockDim.x + threadIdx.x;

    // ebs conversion: 8 contiguous elements per thread
    {
        size_t base = (size_t)e * 8;
        if (base < (size_t)N_TOTAL * DIM) {
            float4 a = *reinterpret_cast<const float4*>(ebs + base);
            float4 b = *reinterpret_cast<const float4*>(ebs + base + 4);
            __half2 h[4];
            h[0] = __float22half2_rn(make_float2(a.x, a.y));
            h[1] = __float22half2_rn(make_float2(a.z, a.w));
            h[2] = __float22half2_rn(make_float2(b.x, b.y));
            h[3] = __float22half2_rn(make_float2(b.z, b.w));
            *reinterpret_cast<uint4*>(g_ebs_h + base) =
                *reinterpret_cast<uint4*>(h);
        }
    }

    // W conversion (first 16384 threads)
    if (e < DIM * DIM) {
        int k = e >> 7, col = e & 127;
        int lq = col >> 4, n = col & 15;
        int src = k * DIM + n * 8 + lq;
        g_wt[0][e] = cvt_tf32(__ldg(Wu + src));
        g_wt[1][e] = cvt_tf32(__ldg(Wi + src));
    }

    // histogram
    if (e < E_u) {
        atomicAdd(&g_cnt[__ldg(rows_u + e)], 1);
    } else {
        int e2 = e - E_u;
        if (e2 < E_i) atomicAdd(&g_cnt[N_USER + __ldg(rows_i + e2)], 1);
    }
}

// ---------------------------------------------------------------------------
// 2a) per-tile sums
// ---------------------------------------------------------------------------
__global__ void scanA_kernel() {
    __shared__ int red[256];
    int t = threadIdx.x;
    int base = blockIdx.x * SCAN_TILE + t * 4;
    int s = 0;
    if (base + 3 < N_TOTAL) {
        int4 v = *reinterpret_cast<const int4*>(&g_cnt[base]);
        s = v.x + v.y + v.z + v.w;
    } else {
#pragma unroll
        for (int i = 0; i < 4; i++)
            if (base + i < N_TOTAL) s += g_cnt[base + i];
    }
    red[t] = s;
    __syncthreads();
#pragma unroll
    for (int d = 128; d > 0; d >>= 1) {
        if (t < d) red[t] += red[t + d];
        __syncthreads();
    }
    if (t == 0) g_bsum[blockIdx.x] = red[0];
}

// ---------------------------------------------------------------------------
// 2b) scan the 98 tile sums
// ---------------------------------------------------------------------------
__global__ void scanB_kernel() {
    __shared__ int s[128];
    int t = threadIdx.x;
    int v = (t < NBLK) ? g_bsum[t] : 0;
    s[t] = v;
    __syncthreads();
#pragma unroll
    for (int d = 1; d < 128; d <<= 1) {
        int x = (t >= d) ? s[t - d] : 0;
        __syncthreads();
        s[t] += x;
        __syncthreads();
    }
    if (t < NBLK) g_bpre[t] = s[t] - v;
    if (t == 127) g_off[N_TOTAL] = s[127];
}

// ---------------------------------------------------------------------------
// 2c) tile-local exclusive scan + write g_off/g_cur
// ---------------------------------------------------------------------------
__global__ void scanC_kernel() {
    __shared__ int red[256];
    int t = threadIdx.x;
    int base = blockIdx.x * SCAN_TILE + t * 4;
    int v[4];
    int s = 0;
    if (base + 3 < N_TOTAL) {
        int4 q = *reinterpret_cast<const int4*>(&g_cnt[base]);
        v[0] = q.x; v[1] = q.y; v[2] = q.z; v[3] = q.w;
        s = q.x + q.y + q.z + q.w;
    } else {
#pragma unroll
        for (int i = 0; i < 4; i++) {
            v[i] = (base + i < N_TOTAL) ? g_cnt[base + i] : 0;
            s += v[i];
        }
    }
    red[t] = s;
    __syncthreads();
#pragma unroll
    for (int d = 1; d < 256; d <<= 1) {
        int x = (t >= d) ? red[t - d] : 0;
        __syncthreads();
        red[t] += x;
        __syncthreads();
    }
    int run = red[t] - s + g_bpre[blockIdx.x];
#pragma unroll
    for (int i = 0; i < 4; i++) {
        if (base + i < N_TOTAL) {
            g_off[base + i] = run;
            g_cur[base + i] = run;
            run += v[i];
        }
    }
}

// ---------------------------------------------------------------------------
// 3) permute edges into row-sorted order; pack warp-local row (r&7) in col
// ---------------------------------------------------------------------------
__global__ void permute_kernel(const int*   __restrict__ rows_u,
                               const int*   __restrict__ cols_u,
                               const float* __restrict__ vals_u,
                               const int*   __restrict__ rows_i,
                               const int*   __restrict__ cols_i,
                               const float* __restrict__ vals_i,
                               int E_u, int E_i) {
    int e = blockIdx.x * blockDim.x + threadIdx.x;
    int r, c; float v;
    if (e < E_u) {
        r = __ldg(rows_u + e);
        c = __ldg(cols_u + e);
        v = __ldg(vals_u + e);
    } else {
        e -= E_u;
        if (e >= E_i) return;
        r = N_USER + __ldg(rows_i + e);
        c = __ldg(cols_i + e);
        v = __ldg(vals_i + e);
    }
    int pos = atomicAdd(&g_cur[r], 1);
    g_edge[pos] = make_int2(c | ((r & 7) << 17), __float_as_int(v));
}

// ---------------------------------------------------------------------------
// 4) Fused: contiguous-stream fp16 gather with double-buffered edge prefetch
//    + flush-on-row-change register accumulate -> smem, then TF32 MMA GEMM
//    (B fragments from L2-hot g_wt). ReLU -> d_out.
// ---------------------------------------------------------------------------
__global__ __launch_bounds__(256, 3)
void fused_kernel(float* __restrict__ out) {
    __shared__ float As[RB][AS_PITCH];   // 33792 bytes

    int b = blockIdx.x;
    int entity = (b >= BLOCKS_ENT) ? 1 : 0;
    int lb = b - entity * BLOCKS_ENT;
    int lrow0 = lb * RB;

    int tid  = threadIdx.x;
    int w    = tid >> 5;
    int lane = tid & 31;

    // tail duty: re-zero g_cnt for next call
    {
        int i = b * 64 + (tid & 63);
        if (tid < 64 && i < N_TOTAL) g_cnt[i] = 0;
    }

    int w8 = w * 8;

    // zero this warp's 8 accumulator rows (empty rows must stay zero)
#pragma unroll
    for (int r = 0; r < 8; r++)
        *reinterpret_cast<float4*>(&As[w8 + r][lane * 4]) =
            make_float4(0.f, 0.f, 0.f, 0.f);

    // ---- gather-accumulate over warp's contiguous edge stream ----
    {
        int gbase = entity * N_ENT;
        int r0 = min(lrow0 + w8,     N_ENT);
        int r1 = min(lrow0 + w8 + 8, N_ENT);
        int start = g_off[gbase + r0];
        int end   = g_off[gbase + r1];

        int cur = -1;
        float4 acc = make_float4(0.f, 0.f, 0.f, 0.f);

        int2 ecur[8];
        {
            int m0 = min(8, end - start);
#pragma unroll
            for (int k = 0; k < 8; k++)
                if (k < m0) ecur[k] = __ldg(g_edge + start + k);
        }

        for (int j = start; j < end; j += 8) {
            int m = min(8, end - j);

            // gathers for current batch (dependent only on ecur)
            uint2 gh[8];
#pragma unroll
            for (int k = 0; k < 8; k++)
                if (k < m)
                    gh[k] = *reinterpret_cast<const uint2*>(
                        g_ebs_h + (size_t)(ecur[k].x & 0x1FFFF) * DIM + lane * 4);

            // prefetch next batch's edges (independent -> overlaps gathers)
            int2 enext[8];
            {
                int mn = min(8, end - (j + 8));
#pragma unroll
                for (int k = 0; k < 8; k++)
                    if (k < mn) enext[k] = __ldg(g_edge + j + 8 + k);
            }

            // accumulate with flush-on-row-change (warp-uniform branch)
#pragma unroll
            for (int k = 0; k < 8; k++)
                if (k < m) {
                    int rr = ((unsigned)ecur[k].x) >> 17;
                    if (rr != cur) {
                        if (cur >= 0)
                            *reinterpret_cast<float4*>(&As[w8 + cur][lane * 4]) = acc;
                        acc = make_float4(0.f, 0.f, 0.f, 0.f);
                        cur = rr;
                    }
                    float v = __int_as_float(ecur[k].y);
                    float2 f0 = __half22float2(*reinterpret_cast<__half2*>(&gh[k].x));
                    float2 f1 = __half22float2(*reinterpret_cast<__half2*>(&gh[k].y));
                    acc.x = fmaf(v, f0.x, acc.x);
                    acc.y = fmaf(v, f0.y, acc.y);
                    acc.z = fmaf(v, f1.x, acc.z);
                    acc.w = fmaf(v, f1.y, acc.w);
                }

#pragma unroll
            for (int k = 0; k < 8; k++) ecur[k] = enext[k];
        }
        if (cur >= 0)
            *reinterpret_cast<float4*>(&As[w8 + cur][lane * 4]) = acc;
    }
    __syncthreads();

    // ---- TF32 MMA GEMM + ReLU; B fragments from L2-hot g_wt ----
    int rg = w >> 1;
    int ch = w & 1;
    int lq = lane >> 2;
    int lr = lane & 3;

    int rloc  = rg * 16 + lq;
    int rloc2 = rloc + 8;
    int lrowA  = lrow0 + rloc;
    int lrowA2 = lrow0 + rloc2;
    bool va  = lrowA  < N_ENT;
    bool va2 = lrowA2 < N_ENT;
    float* O = out + (size_t)entity * N_ENT * DIM;
    const unsigned* Wt = g_wt[entity];

    float acc[8][4];
#pragma unroll
    for (int n = 0; n < 8; n++)
#pragma unroll
        for (int j = 0; j < 4; j++) acc[n][j] = 0.f;

#pragma unroll 1
    for (int ks = 0; ks < 16; ks++) {
        int k0 = ks * 8;
        unsigned a0 = cvt_tf32(As[rloc ][k0 + lr]);
        unsigned a1 = cvt_tf32(As[rloc2][k0 + lr]);
        unsigned a2 = cvt_tf32(As[rloc ][k0 + 4 + lr]);
        unsigned a3 = cvt_tf32(As[rloc2][k0 + 4 + lr]);

        uint4 b0q[2], b1q[2];
        {
            const uint4* w0 = reinterpret_cast<const uint4*>(
                Wt + (k0 + lr) * DIM + lq * 16 + ch * 8);
            const uint4* w1 = reinterpret_cast<const uint4*>(
                Wt + (k0 + 4 + lr) * DIM + lq * 16 + ch * 8);
            b0q[0] = __ldg(w0);     b0q[1] = __ldg(w0 + 1);
            b1q[0] = __ldg(w1);     b1q[1] = __ldg(w1 + 1);
        }
        const unsigned* bw0 = reinterpret_cast<const unsigned*>(b0q);
        const unsigned* bw1 = reinterpret_cast<const unsigned*>(b1q);

#pragma unroll
        for (int n = 0; n < 8; n++) {
            asm volatile(
                "mma.sync.aligned.m16n8k8.row.col.f32.tf32.tf32.f32 "
                "{%0,%1,%2,%3}, {%4,%5,%6,%7}, {%8,%9}, {%0,%1,%2,%3};\n"
                : "+f"(acc[n][0]), "+f"(acc[n][1]), "+f"(acc[n][2]), "+f"(acc[n][3])
                : "r"(a0), "r"(a1), "r"(a2), "r"(a3), "r"(bw0[n]), "r"(bw1[n]));
        }
    }

#pragma unroll
    for (int n = 0; n < 8; n++) {
        int col = (ch * 8 + n) * 8 + lr * 2;
        if (va) {
            float2 o;
            o.x = fmaxf(acc[n][0], 0.f);
            o.y = fmaxf(acc[n][1], 0.f);
            *reinterpret_cast<float2*>(O + (size_t)lrowA * DIM + col) = o;
        }
        if (va2) {
            float2 o;
            o.x = fmaxf(acc[n][2], 0.f);
            o.y = fmaxf(acc[n][3], 0.f);
            *reinterpret_cast<float2*>(O + (size_t)lrowA2 * DIM + col) = o;
        }
    }
}

// ---------------------------------------------------------------------------
extern "C" void kernel_launch(void* const* d_in, const int* in_sizes, int n_in,
                              void* d_out, int out_size) {
    const float* ebs    = (const float*)d_in[0];
    const int*   rows_u = (const int*)  d_in[1];
    const int*   cols_u = (const int*)  d_in[2];
    const float* vals_u = (const float*)d_in[3];
    const float* W_u    = (const float*)d_in[4];
    const int*   rows_i = (const int*)  d_in[5];
    const int*   cols_i = (const int*)  d_in[6];
    const float* vals_i = (const float*)d_in[7];
    const float* W_i    = (const float*)d_in[8];
    float* out = (float*)d_out;

    int E_u = in_sizes[1];
    int E_i = in_sizes[5];
    int E_total = E_u + E_i;

    prep_kernel<<<(E_total + 255) / 256, 256>>>(rows_u, rows_i, W_u, W_i, ebs,
                                                E_u, E_i);
    scanA_kernel<<<NBLK, 256>>>();
    scanB_kernel<<<1, 128>>>();
    scanC_kernel<<<NBLK, 256>>>();
    permute_kernel<<<(E_total + 255) / 256, 256>>>(rows_u, cols_u, vals_u,
                                                   rows_i, cols_i, vals_i,
                                                   E_u, E_i);
    fused_kernel<<<2 * BLOCKS_ENT, 256>>>(out);
}

// round 17
// speedup vs baseline: 1.0950x; 1.0950x over previous
#include <cuda_runtime.h>
#include <cuda_fp16.h>
#include <cstdint>

#define N_TOTAL 100000
#define DIM     128
#define N_USER  50000
#define N_ENT   50000
#define E_MAX   1700000
#define RB      64                 // rows per block
#define BLOCKS_ENT 782             // ceil(50000/64)
#define AS_PITCH 132
#define SCAN_TILE 1024
#define NBLK 98                    // ceil(100000/1024)

// Scratch (device globals; zero-initialized at load).
// g_cnt re-zeroed by fused_kernel tail each call.
__device__ int      g_cnt[N_TOTAL];
__device__ int      g_off[N_TOTAL + 1];
__device__ int      g_cur[N_TOTAL];
__device__ int      g_bsum[NBLK];
__device__ int      g_bpre[NBLK];
__device__ int2     g_edge[E_MAX];               // {col, val_bits}
__device__ unsigned g_wt[2][DIM * DIM];          // W tf32, permuted [k][lq*16+n]
__device__ __half   g_ebs_h[(size_t)N_TOTAL * DIM];  // fp16 embeddings (25.6MB)

__device__ __forceinline__ unsigned cvt_tf32(float f) {
    unsigned r;
    asm("cvt.rna.tf32.f32 %0, %1;" : "=r"(r) : "f"(f));
    return r;
}

// ---------------------------------------------------------------------------
// 1) prep: ebs fp32->fp16, W->tf32 permuted, row histogram  (one kernel)
// ---------------------------------------------------------------------------
__global__ void prep_kernel(const int* __restrict__ rows_u,
                            const int* __restrict__ rows_i,
                            const float* __restrict__ Wu,
                            const float* __restrict__ Wi,
                            const float* __restrict__ ebs,
                            int E_u, int E_i) {
    int e = blockIdx.x * blockDim.x + threadIdx.x;

    // ebs conversion: 8 contiguous elements per thread
    {
        size_t base = (size_t)e * 8;
        if (base < (size_t)N_TOTAL * DIM) {
            float4 a = *reinterpret_cast<const float4*>(ebs + base);
            float4 b = *reinterpret_cast<const float4*>(ebs + base + 4);
            __half2 h[4];
            h[0] = __float22half2_rn(make_float2(a.x, a.y));
            h[1] = __float22half2_rn(make_float2(a.z, a.w));
            h[2] = __float22half2_rn(make_float2(b.x, b.y));
            h[3] = __float22half2_rn(make_float2(b.z, b.w));
            *reinterpret_cast<uint4*>(g_ebs_h + base) =
                *reinterpret_cast<uint4*>(h);
        }
    }

    // W conversion (first 16384 threads)
    if (e < DIM * DIM) {
        int k = e >> 7, col = e & 127;
        int lq = col >> 4, n = col & 15;
        int src = k * DIM + n * 8 + lq;
        g_wt[0][e] = cvt_tf32(__ldg(Wu + src));
        g_wt[1][e] = cvt_tf32(__ldg(Wi + src));
    }

    // histogram
    if (e < E_u) {
        atomicAdd(&g_cnt[__ldg(rows_u + e)], 1);
    } else {
        int e2 = e - E_u;
        if (e2 < E_i) atomicAdd(&g_cnt[N_USER + __ldg(rows_i + e2)], 1);
    }
}

// ---------------------------------------------------------------------------
// 2a) per-tile sums
// ---------------------------------------------------------------------------
__global__ void scanA_kernel() {
    __shared__ int red[256];
    int t = threadIdx.x;
    int base = blockIdx.x * SCAN_TILE + t * 4;
    int s = 0;
    if (base + 3 < N_TOTAL) {
        int4 v = *reinterpret_cast<const int4*>(&g_cnt[base]);
        s = v.x + v.y + v.z + v.w;
    } else {
#pragma unroll
        for (int i = 0; i < 4; i++)
            if (base + i < N_TOTAL) s += g_cnt[base + i];
    }
    red[t] = s;
    __syncthreads();
#pragma unroll
    for (int d = 128; d > 0; d >>= 1) {
        if (t < d) red[t] += red[t + d];
        __syncthreads();
    }
    if (t == 0) g_bsum[blockIdx.x] = red[0];
}

// ---------------------------------------------------------------------------
// 2b) scan the 98 tile sums
// ---------------------------------------------------------------------------
__global__ void scanB_kernel() {
    __shared__ int s[128];
    int t = threadIdx.x;
    int v = (t < NBLK) ? g_bsum[t] : 0;
    s[t] = v;
    __syncthreads();
#pragma unroll
    for (int d = 1; d < 128; d <<= 1) {
        int x = (t >= d) ? s[t - d] : 0;
        __syncthreads();
        s[t] += x;
        __syncthreads();
    }
    if (t < NBLK) g_bpre[t] = s[t] - v;
    if (t == 127) g_off[N_TOTAL] = s[127];
}

// ---------------------------------------------------------------------------
// 2c) tile-local exclusive scan + write g_off/g_cur
// ---------------------------------------------------------------------------
__global__ void scanC_kernel() {
    __shared__ int red[256];
    int t = threadIdx.x;
    int base = blockIdx.x * SCAN_TILE + t * 4;
    int v[4];
    int s = 0;
    if (base + 3 < N_TOTAL) {
        int4 q = *reinterpret_cast<const int4*>(&g_cnt[base]);
        v[0] = q.x; v[1] = q.y; v[2] = q.z; v[3] = q.w;
        s = q.x + q.y + q.z + q.w;
    } else {
#pragma unroll
        for (int i = 0; i < 4; i++) {
            v[i] = (base + i < N_TOTAL) ? g_cnt[base + i] : 0;
            s += v[i];
        }
    }
    red[t] = s;
    __syncthreads();
#pragma unroll
    for (int d = 1; d < 256; d <<= 1) {
        int x = (t >= d) ? red[t - d] : 0;
        __syncthreads();
        red[t] += x;
        __syncthreads();
    }
    int run = red[t] - s + g_bpre[blockIdx.x];
#pragma unroll
    for (int i = 0; i < 4; i++) {
        if (base + i < N_TOTAL) {
            g_off[base + i] = run;
            g_cur[base + i] = run;
            run += v[i];
        }
    }
}

// ---------------------------------------------------------------------------
// 3) permute edges into row-sorted order
// ---------------------------------------------------------------------------
__global__ void permute_kernel(const int*   __restrict__ rows_u,
                               const int*   __restrict__ cols_u,
                               const float* __restrict__ vals_u,
                               const int*   __restrict__ rows_i,
                               const int*   __restrict__ cols_i,
                               const float* __restrict__ vals_i,
                               int E_u, int E_i) {
    int e = blockIdx.x * blockDim.x + threadIdx.x;
    int r, c; float v;
    if (e < E_u) {
        r = __ldg(rows_u + e);
        c = __ldg(cols_u + e);
        v = __ldg(vals_u + e);
    } else {
        e -= E_u;
        if (e >= E_i) return;
        r = N_USER + __ldg(rows_i + e);
        c = __ldg(cols_i + e);
        v = __ldg(vals_i + e);
    }
    int pos = atomicAdd(&g_cur[r], 1);
    g_edge[pos] = make_int2(c, __float_as_int(v));
}

// ---------------------------------------------------------------------------
// 4) Fused: per-row fp16 gather with smem-staged edges (one coalesced
//    lane-indexed edge load per 32 edges; inner batches read edges via LDS),
//    fp32 accumulate -> smem, then TF32 MMA GEMM (B frags from L2-hot g_wt).
// ---------------------------------------------------------------------------
__global__ __launch_bounds__(256, 4)
void fused_kernel(float* __restrict__ out) {
    __shared__ float As[RB][AS_PITCH];   // 33792 bytes
    __shared__ int2  sedge[8][32];       // 2048 bytes, per-warp edge window

    int b = blockIdx.x;
    int entity = (b >= BLOCKS_ENT) ? 1 : 0;
    int lb = b - entity * BLOCKS_ENT;
    int lrow0 = lb * RB;

    int tid  = threadIdx.x;
    int w    = tid >> 5;
    int lane = tid & 31;

    // tail duty: re-zero g_cnt for next call
    {
        int i = b * 64 + (tid & 63);
        if (tid < 64 && i < N_TOTAL) g_cnt[i] = 0;
    }

    // ---- per-row gather-accumulate (fp16 gather, fp32 accumulate) ----
    {
        int gbase = entity * N_ENT;
        int w8 = w * 8;
#pragma unroll 1
        for (int r = 0; r < 8; r++) {
            int lrow = lrow0 + w8 + r;
            int start = g_off[gbase + min(lrow, N_ENT)];
            int end   = g_off[gbase + min(lrow + 1, N_ENT)];
            int cnt   = end - start;

            float4 acc = make_float4(0.f, 0.f, 0.f, 0.f);
#pragma unroll 1
            for (int base = 0; base < cnt; base += 32) {
                int m = min(32, cnt - base);
                if (lane < m)
                    sedge[w][lane] = __ldg(g_edge + start + base + lane);
                __syncwarp();

#pragma unroll 1
                for (int j = 0; j < m; j += 8) {
                    int mm = m - j;   // >=1
                    int2 e[8]; uint2 gh[8];
#pragma unroll
                    for (int k = 0; k < 8; k++)
                        if (k < mm) e[k] = sedge[w][j + k];   // LDS broadcast
#pragma unroll
                    for (int k = 0; k < 8; k++)
                        if (k < mm)
                            gh[k] = *reinterpret_cast<const uint2*>(
                                g_ebs_h + (size_t)e[k].x * DIM + lane * 4);
#pragma unroll
                    for (int k = 0; k < 8; k++)
                        if (k < mm) {
                            float v = __int_as_float(e[k].y);
                            float2 f0 = __half22float2(
                                *reinterpret_cast<__half2*>(&gh[k].x));
                            float2 f1 = __half22float2(
                                *reinterpret_cast<__half2*>(&gh[k].y));
                            acc.x = fmaf(v, f0.x, acc.x);
                            acc.y = fmaf(v, f0.y, acc.y);
                            acc.z = fmaf(v, f1.x, acc.z);
                            acc.w = fmaf(v, f1.y, acc.w);
                        }
                }
                __syncwarp();
            }
            *reinterpret_cast<float4*>(&As[w8 + r][lane * 4]) = acc;
        }
    }
    __syncthreads();

    // ---- TF32 MMA GEMM + ReLU; B fragments from L2-hot g_wt ----
    int rg = w >> 1;
    int ch = w & 1;
    int lq = lane >> 2;
    int lr = lane & 3;

    int rloc  = rg * 16 + lq;
    int rloc2 = rloc + 8;
    int lrowA  = lrow0 + rloc;
    int lrowA2 = lrow0 + rloc2;
    bool va  = lrowA  < N_ENT;
    bool va2 = lrowA2 < N_ENT;
    float* O = out + (size_t)entity * N_ENT * DIM;
    const unsigned* Wt = g_wt[entity];

    float acc[8][4];
#pragma unroll
    for (int n = 0; n < 8; n++)
#pragma unroll
        for (int j = 0; j < 4; j++) acc[n][j] = 0.f;

#pragma unroll 1
    for (int ks = 0; ks < 16; ks++) {
        int k0 = ks * 8;
        unsigned a0 = cvt_tf32(As[rloc ][k0 + lr]);
        unsigned a1 = cvt_tf32(As[rloc2][k0 + lr]);
        unsigned a2 = cvt_tf32(As[rloc ][k0 + 4 + lr]);
        unsigned a3 = cvt_tf32(As[rloc2][k0 + 4 + lr]);

        // B fragments: 4 x LDG.128 from g_wt (L2-hot, pre-permuted tf32)
        uint4 b0q[2], b1q[2];
        {
            const uint4* w0 = reinterpret_cast<const uint4*>(
                Wt + (k0 + lr) * DIM + lq * 16 + ch * 8);
            const uint4* w1 = reinterpret_cast<const uint4*>(
                Wt + (k0 + 4 + lr) * DIM + lq * 16 + ch * 8);
            b0q[0] = __ldg(w0);     b0q[1] = __ldg(w0 + 1);
            b1q[0] = __ldg(w1);     b1q[1] = __ldg(w1 + 1);
        }
        const unsigned* bw0 = reinterpret_cast<const unsigned*>(b0q);
        const unsigned* bw1 = reinterpret_cast<const unsigned*>(b1q);

#pragma unroll
        for (int n = 0; n < 8; n++) {
            asm volatile(
                "mma.sync.aligned.m16n8k8.row.col.f32.tf32.tf32.f32 "
                "{%0,%1,%2,%3}, {%4,%5,%6,%7}, {%8,%9}, {%0,%1,%2,%3};\n"
                : "+f"(acc[n][0]), "+f"(acc[n][1]), "+f"(acc[n][2]), "+f"(acc[n][3])
                : "r"(a0), "r"(a1), "r"(a2), "r"(a3), "r"(bw0[n]), "r"(bw1[n]));
        }
    }

#pragma unroll
    for (int n = 0; n < 8; n++) {
        int col = (ch * 8 + n) * 8 + lr * 2;
        if (va) {
            float2 o;
            o.x = fmaxf(acc[n][0], 0.f);
            o.y = fmaxf(acc[n][1], 0.f);
            *reinterpret_cast<float2*>(O + (size_t)lrowA * DIM + col) = o;
        }
        if (va2) {
            float2 o;
            o.x = fmaxf(acc[n][2], 0.f);
            o.y = fmaxf(acc[n][3], 0.f);
            *reinterpret_cast<float2*>(O + (size_t)lrowA2 * DIM + col) = o;
        }
    }
}

// ---------------------------------------------------------------------------
extern "C" void kernel_launch(void* const* d_in, const int* in_sizes, int n_in,
                              void* d_out, int out_size) {
    const float* ebs    = (const float*)d_in[0];
    const int*   rows_u = (const int*)  d_in[1];
    const int*   cols_u = (const int*)  d_in[2];
    const float* vals_u = (const float*)d_in[3];
    const float* W_u    = (const float*)d_in[4];
    const int*   rows_i = (const int*)  d_in[5];
    const int*   cols_i = (const int*)  d_in[6];
    const float* vals_i = (const float*)d_in[7];
    const float* W_i    = (const float*)d_in[8];
    float* out = (float*)d_out;

    int E_u = in_sizes[1];
    int E_i = in_sizes[5];
    int E_total = E_u + E_i;

    prep_kernel<<<(E_total + 255) / 256, 256>>>(rows_u, rows_i, W_u, W_i, ebs,
                                                E_u, E_i);
    scanA_kernel<<<NBLK, 256>>>();
    scanB_kernel<<<1, 128>>>();
    scanC_kernel<<<NBLK, 256>>>();
    permute_kernel<<<(E_total + 255) / 256, 256>>>(rows_u, cols_u, vals_u,
                                                   rows_i, cols_i, vals_i,
                                                   E_u, E_i);
    fused_kernel<<<2 * BLOCKS_ENT, 256>>>(out);
}